// round 1
// baseline (speedup 1.0000x reference)
#include <cuda_runtime.h>
#include <cstddef>

#define NB 4
#define NN 512
#define NE 512
#define NH 32
#define ND 16
#define NP 128
#define CW 1088          // scratch C width: [q 512 | k 512 | w 32 | pad 32]
#define JT 128           // j-tile in fused kernel

// ---------------- device scratch (no allocations allowed) ----------------
__device__ float g_xn[NB * NN * NE];        // layernormed query, 4 MB
__device__ float g_Wcat[CW * NE];           // concatenated weights, 2.2 MB
__device__ float g_C[NB * NN * CW];         // q|k|w per token, 8.9 MB (L2 resident)
__device__ float g_wbg[NP * NH];            // Wb*pln_g transposed [p][h]
__device__ float g_c1[NH];
__device__ float g_c2[NH];

// ---------------- prep: build Wcat, wbg, c1, c2 ----------------
__global__ void prep_kernel(const float* __restrict__ Wq, const float* __restrict__ Wk,
                            const float* __restrict__ Wv, const float* __restrict__ Wf,
                            const float* __restrict__ Wb, const float* __restrict__ bb,
                            const float* __restrict__ pg, const float* __restrict__ pb)
{
    int r = blockIdx.x;
    int tid = threadIdx.x;
    if (r < 512) {
        for (int e = tid; e < NE; e += 256)
            g_Wcat[r * NE + e] = Wq[r * NE + e] * 0.25f;   // SCALING = D^-0.5 folded in
    } else if (r < 1024) {
        int rr = r - 512;
        for (int e = tid; e < NE; e += 256)
            g_Wcat[r * NE + e] = Wk[rr * NE + e];
    } else if (r < 1056) {
        int h = r - 1024;
        for (int e = tid; e < NE; e += 256) {
            float s = 0.f;
#pragma unroll
            for (int d = 0; d < ND; d++)
                s += Wf[h * ND + d] * Wv[(h * ND + d) * NE + e];
            g_Wcat[r * NE + e] = s;                        // Wvf
        }
    } else if (r < 1088) {
        for (int e = tid; e < NE; e += 256) g_Wcat[r * NE + e] = 0.f;
    } else if (r == 1088) {
        for (int t = tid; t < NP * NH; t += 256) {
            int p = t >> 5, h = t & 31;
            g_wbg[t] = Wb[h * NP + p] * pg[p];             // [p][h]
        }
    } else {
        if (tid < NH) {
            int h = tid;
            float s1 = 0.f, s2 = 0.f;
            for (int p = 0; p < NP; p++) {
                float wv = Wb[h * NP + p];
                s1 += wv * pg[p];
                s2 += wv * pb[p];
            }
            g_c1[h] = s1;
            g_c2[h] = s2 + bb[h];
        }
    }
}

// ---------------- layernorm over E=512, one row per block (128 threads) ----------------
__global__ void ln_kernel(const float* __restrict__ q, const float* __restrict__ g,
                          const float* __restrict__ b)
{
    int row = blockIdx.x;
    int tid = threadIdx.x;
    const float* x = q + (size_t)row * NE;
    float4 v = *(const float4*)(x + tid * 4);
    float s  = v.x + v.y + v.z + v.w;
    float ss = v.x * v.x + v.y * v.y + v.z * v.z + v.w * v.w;
#pragma unroll
    for (int o = 16; o; o >>= 1) {
        s  += __shfl_xor_sync(0xffffffffu, s, o);
        ss += __shfl_xor_sync(0xffffffffu, ss, o);
    }
    __shared__ float rs[4], rss[4];
    int w = tid >> 5;
    if ((tid & 31) == 0) { rs[w] = s; rss[w] = ss; }
    __syncthreads();
    s  = rs[0] + rs[1] + rs[2] + rs[3];
    ss = rss[0] + rss[1] + rss[2] + rss[3];
    float mu   = s * (1.f / 512.f);
    float var  = ss * (1.f / 512.f) - mu * mu;
    float rstd = rsqrtf(var + 1e-5f);
    float4 gg = *(const float4*)(g + tid * 4);
    float4 bv = *(const float4*)(b + tid * 4);
    float4 o;
    o.x = (v.x - mu) * rstd * gg.x + bv.x;
    o.y = (v.y - mu) * rstd * gg.y + bv.y;
    o.z = (v.z - mu) * rstd * gg.z + bv.z;
    o.w = (v.w - mu) * rstd * gg.w + bv.w;
    *(float4*)(g_xn + (size_t)row * NE + tid * 4) = o;
}

// ---------------- GEMM: C[2048][1088] = xn[2048][512] @ Wcat[1088][512]^T ----------------
// BM=BN=64, BK=16, 256 threads, 4x4 microtile
__global__ __launch_bounds__(256) void gemm_qkw_kernel()
{
    __shared__ float As[16][68];
    __shared__ float Bs[16][68];
    int m0 = blockIdx.x * 64, n0 = blockIdx.y * 64;
    int tid = threadIdx.x;
    int tm = tid >> 4, tn = tid & 15;
    int lr = tid >> 2, lc = tid & 3;
    float acc[4][4] = {};
    for (int k0 = 0; k0 < NE; k0 += 16) {
        float4 av = *(const float4*)&g_xn[(size_t)(m0 + lr) * NE + k0 + lc * 4];
        float4 bv = *(const float4*)&g_Wcat[(size_t)(n0 + lr) * NE + k0 + lc * 4];
        As[lc * 4 + 0][lr] = av.x; As[lc * 4 + 1][lr] = av.y;
        As[lc * 4 + 2][lr] = av.z; As[lc * 4 + 3][lr] = av.w;
        Bs[lc * 4 + 0][lr] = bv.x; Bs[lc * 4 + 1][lr] = bv.y;
        Bs[lc * 4 + 2][lr] = bv.z; Bs[lc * 4 + 3][lr] = bv.w;
        __syncthreads();
#pragma unroll
        for (int k = 0; k < 16; k++) {
            float4 a = *(const float4*)&As[k][tm * 4];
            float4 b = *(const float4*)&Bs[k][tn * 4];
            acc[0][0] += a.x * b.x; acc[0][1] += a.x * b.y; acc[0][2] += a.x * b.z; acc[0][3] += a.x * b.w;
            acc[1][0] += a.y * b.x; acc[1][1] += a.y * b.y; acc[1][2] += a.y * b.z; acc[1][3] += a.y * b.w;
            acc[2][0] += a.z * b.x; acc[2][1] += a.z * b.y; acc[2][2] += a.z * b.z; acc[2][3] += a.z * b.w;
            acc[3][0] += a.w * b.x; acc[3][1] += a.w * b.y; acc[3][2] += a.w * b.z; acc[3][3] += a.w * b.w;
        }
        __syncthreads();
    }
#pragma unroll
    for (int t = 0; t < 4; t++)
#pragma unroll
        for (int u = 0; u < 4; u++)
            g_C[(size_t)(m0 + tm * 4 + t) * CW + n0 + tn * 4 + u] = acc[t][u];
}

// ---------------- fused attention kernel: one CTA per (b, i) ----------------
// smem layout (floats):
//   pair_s [128][132]   16896
//   L      [32][516]    16512
//   wbg_s  [128][32]     4096
//   q_s    [512]          512
//   mu_s   [128], rs_s [128]
//   c1_s[32], c2_s[32], invZ_s[32], red_s[32]
#define SM_FLOATS (16896 + 16512 + 4096 + 512 + 128 + 128 + 32 + 32 + 32 + 32)

__global__ __launch_bounds__(256) void fused_attn_kernel(
    const float* __restrict__ pair, const float* __restrict__ mask,
    const float* __restrict__ dpos, float* __restrict__ out)
{
    extern __shared__ float sm[];
    float* pair_s = sm;                       // [j][132]
    float* L      = pair_s + 128 * 132;       // [h][516]
    float* wbg_s  = L + 32 * 516;             // [p][32]
    float* q_s    = wbg_s + 128 * 32;
    float* mu_s   = q_s + 512;
    float* rs_s   = mu_s + 128;
    float* c1_s   = rs_s + 128;
    float* c2_s   = c1_s + 32;
    float* invZ_s = c2_s + 32;
    float* red_s  = invZ_s + 32;

    int bi = blockIdx.x;                      // b*512 + i
    int b = bi >> 9, i = bi & 511;
    int tid = threadIdx.x;

    const float* crow = g_C + (size_t)bi * CW;            // q row for (b,i)
    for (int e = tid; e < 512; e += 256) q_s[e] = crow[e];
    for (int t = tid; t < NP * NH; t += 256) wbg_s[t] = g_wbg[t];
    if (tid < 32) { c1_s[tid] = g_c1[tid]; c2_s[tid] = g_c2[tid]; }

    const float* pbase = pair + (size_t)bi * NN * NP;     // pair[b,i,:,:]
    int jg = tid >> 3, hg = tid & 7;
    int jg4 = jg * 4, hg4 = hg * 4;

    for (int tile = 0; tile < NN / JT; ++tile) {
        int j0 = tile * JT;
        __syncthreads();
        // ---- stage pair tile (coalesced float4 load, conflict-free STS.128) ----
#pragma unroll
        for (int it = 0; it < 16; ++it) {
            int idx = it * 256 + tid;
            int jl = idx >> 5, p4 = idx & 31;
            float4 v = *(const float4*)(pbase + (size_t)(j0 + jl) * NP + p4 * 4);
            *(float4*)&pair_s[jl * 132 + p4 * 4] = v;
        }
        __syncthreads();
        // ---- per-row mean / rstd (raw pair; LN folded into GEMM epilogue) ----
        {
            int row = tid >> 1, half = tid & 1;
            const float* pr = &pair_s[row * 132 + half * 64];
            float s = 0.f, ss = 0.f;
#pragma unroll 8
            for (int p = 0; p < 64; p++) { float v = pr[p]; s += v; ss += v * v; }
            s  += __shfl_xor_sync(0xffffffffu, s, 1);
            ss += __shfl_xor_sync(0xffffffffu, ss, 1);
            if (half == 0) {
                float mu  = s * (1.f / 128.f);
                float var = ss * (1.f / 128.f) - mu * mu;
                mu_s[row] = mu;
                rs_s[row] = rsqrtf(var + 1e-5f);
            }
        }
        __syncthreads();
        // ---- bias GEMM: [128 j] x [32 h], K = 128, 4x4 register tile ----
        float acc[4][4] = {};
        const float* pr0 = &pair_s[(jg4 + 0) * 132];
        const float* pr1 = &pair_s[(jg4 + 1) * 132];
        const float* pr2 = &pair_s[(jg4 + 2) * 132];
        const float* pr3 = &pair_s[(jg4 + 3) * 132];
#pragma unroll 4
        for (int p = 0; p < NP; ++p) {
            float a0 = pr0[p], a1 = pr1[p], a2 = pr2[p], a3 = pr3[p];
            float4 wv = *(const float4*)&wbg_s[p * 32 + hg4];
            acc[0][0] += a0 * wv.x; acc[0][1] += a0 * wv.y; acc[0][2] += a0 * wv.z; acc[0][3] += a0 * wv.w;
            acc[1][0] += a1 * wv.x; acc[1][1] += a1 * wv.y; acc[1][2] += a1 * wv.z; acc[1][3] += a1 * wv.w;
            acc[2][0] += a2 * wv.x; acc[2][1] += a2 * wv.y; acc[2][2] += a2 * wv.z; acc[2][3] += a2 * wv.w;
            acc[3][0] += a3 * wv.x; acc[3][1] += a3 * wv.y; acc[3][2] += a3 * wv.z; acc[3][3] += a3 * wv.w;
        }
        // ---- epilogue: finish LN-bias, add qk logits + mask, write L ----
        const float* krow_base = g_C + ((size_t)(b * NN + j0 + jg4)) * CW + 512;
#pragma unroll
        for (int u = 0; u < 4; u++) {
            int h = hg4 + u;
            float c1v = c1_s[h], c2v = c2_s[h];
            const float* mrow = mask + (((size_t)(b * NH + h) * NN + i) * NN) + j0 + jg4;
            float4 mk = *(const float4*)mrow;
            float mka[4] = { mk.x, mk.y, mk.z, mk.w };
#pragma unroll
            for (int t = 0; t < 4; t++) {
                int jl = jg4 + t;
                const float* kr = krow_base + (size_t)t * CW + h * ND;
                float qk = 0.f;
#pragma unroll
                for (int d = 0; d < ND; d += 4) {
                    float4 kv = *(const float4*)(kr + d);
                    float4 qv = *(const float4*)&q_s[h * ND + d];
                    qk += kv.x * qv.x + kv.y * qv.y + kv.z * qv.z + kv.w * qv.w;
                }
                float lv = rs_s[jl] * (acc[t][u] - mu_s[jl] * c1v) + c2v + qk + mka[t];
                L[h * 516 + j0 + jl] = lv;
            }
        }
    }
    __syncthreads();
    // ---- per-head softmax stats; overwrite L with exp(L - m) ----
    {
        int w = tid >> 5, lane = tid & 31;
#pragma unroll
        for (int hh = 0; hh < 4; hh++) {
            int h = w * 4 + hh;
            float* Lr = &L[h * 516];
            float m = -1e30f;
#pragma unroll
            for (int t = 0; t < 16; t++) m = fmaxf(m, Lr[lane + 32 * t]);
#pragma unroll
            for (int o = 16; o; o >>= 1) m = fmaxf(m, __shfl_xor_sync(0xffffffffu, m, o));
            float z = 0.f;
#pragma unroll
            for (int t = 0; t < 16; t++) {
                int j = lane + 32 * t;
                float e = __expf(Lr[j] - m);
                Lr[j] = e;
                z += e;
            }
#pragma unroll
            for (int o = 16; o; o >>= 1) z += __shfl_xor_sync(0xffffffffu, z, o);
            if (lane == 0) invZ_s[h] = 1.f / z;
        }
    }
    __syncthreads();
    // ---- mix heads with w, contract with delta_pos ----
    float fc0 = 0.f, fc1 = 0.f, fc2 = 0.f;
#pragma unroll
    for (int jj = 0; jj < 2; jj++) {
        int j = tid + jj * 256;
        const float* wr = g_C + ((size_t)(b * NN + j)) * CW + 1024;
        float s = 0.f;
#pragma unroll
        for (int h = 0; h < NH; h++)
            s += L[h * 516 + j] * invZ_s[h] * wr[h];
        const float* dp = dpos + ((size_t)bi * NN + j) * 3;
        fc0 += s * dp[0];
        fc1 += s * dp[1];
        fc2 += s * dp[2];
    }
#pragma unroll
    for (int o = 16; o; o >>= 1) {
        fc0 += __shfl_xor_sync(0xffffffffu, fc0, o);
        fc1 += __shfl_xor_sync(0xffffffffu, fc1, o);
        fc2 += __shfl_xor_sync(0xffffffffu, fc2, o);
    }
    {
        int w = tid >> 5, lane = tid & 31;
        if (lane == 0) { red_s[w] = fc0; red_s[8 + w] = fc1; red_s[16 + w] = fc2; }
    }
    __syncthreads();
    if (tid < 3) {
        float s = 0.f;
#pragma unroll
        for (int w = 0; w < 8; w++) s += red_s[tid * 8 + w];
        out[(size_t)bi * 3 + tid] = s;
    }
}

// ---------------- launcher ----------------
extern "C" void kernel_launch(void* const* d_in, const int* in_sizes, int n_in,
                              void* d_out, int out_size)
{
    (void)in_sizes; (void)n_in; (void)out_size;
    const float* query  = (const float*)d_in[0];
    const float* pair   = (const float*)d_in[1];
    const float* mask   = (const float*)d_in[2];
    const float* dpos   = (const float*)d_in[3];
    const float* ln_g   = (const float*)d_in[4];
    const float* ln_b   = (const float*)d_in[5];
    const float* Wq     = (const float*)d_in[6];
    const float* Wk     = (const float*)d_in[7];
    const float* Wv     = (const float*)d_in[8];
    const float* pln_g  = (const float*)d_in[9];
    const float* pln_b  = (const float*)d_in[10];
    const float* Wb     = (const float*)d_in[11];
    const float* bb     = (const float*)d_in[12];
    const float* Wf     = (const float*)d_in[13];
    float* out = (float*)d_out;

    static_assert(SM_FLOATS * 4 <= 200 * 1024, "smem budget");
    cudaFuncSetAttribute(fused_attn_kernel,
                         cudaFuncAttributeMaxDynamicSharedMemorySize, SM_FLOATS * 4);

    prep_kernel<<<1090, 256>>>(Wq, Wk, Wv, Wf, Wb, bb, pln_g, pln_b);
    ln_kernel<<<NB * NN, 128>>>(query, ln_g, ln_b);
    gemm_qkw_kernel<<<dim3(32, 17), 256>>>();
    fused_attn_kernel<<<NB * NN, 256, SM_FLOATS * 4>>>(pair, mask, dpos, out);
}

// round 2
// speedup vs baseline: 1.3605x; 1.3605x over previous
#include <cuda_runtime.h>
#include <cstddef>

#define NB 4
#define NN 512
#define NE 512
#define NH 32
#define ND 16
#define NP 128
#define CW 1088          // scratch C width: [q 512 | k 512 | w 32 | pad 32]
#define JT 64            // j-tile in fused kernel
#define NTILE (NN / JT)  // 8

// ---------------- device scratch (no allocations allowed) ----------------
__device__ float g_xn[NB * NN * NE];        // layernormed query, 4 MB
__device__ float g_Wcat[CW * NE];           // concatenated weights, 2.2 MB
__device__ float g_C[NB * NN * CW];         // q|k|w per token, 8.9 MB (L2 resident)
__device__ float g_wbg[NP * NH];            // Wb*pln_g transposed [p][h]
__device__ float g_c1[NH];
__device__ float g_c2[NH];

// ---------------- prep: build Wcat, wbg, c1, c2 ----------------
__global__ void prep_kernel(const float* __restrict__ Wq, const float* __restrict__ Wk,
                            const float* __restrict__ Wv, const float* __restrict__ Wf,
                            const float* __restrict__ Wb, const float* __restrict__ bb,
                            const float* __restrict__ pg, const float* __restrict__ pb)
{
    int r = blockIdx.x;
    int tid = threadIdx.x;
    if (r < 512) {
        for (int e = tid; e < NE; e += 256)
            g_Wcat[r * NE + e] = Wq[r * NE + e] * 0.25f;   // SCALING = D^-0.5 folded in
    } else if (r < 1024) {
        int rr = r - 512;
        for (int e = tid; e < NE; e += 256)
            g_Wcat[r * NE + e] = Wk[rr * NE + e];
    } else if (r < 1056) {
        int h = r - 1024;
        for (int e = tid; e < NE; e += 256) {
            float s = 0.f;
#pragma unroll
            for (int d = 0; d < ND; d++)
                s += Wf[h * ND + d] * Wv[(h * ND + d) * NE + e];
            g_Wcat[r * NE + e] = s;                        // Wvf
        }
    } else if (r < 1088) {
        for (int e = tid; e < NE; e += 256) g_Wcat[r * NE + e] = 0.f;
    } else if (r == 1088) {
        for (int t = tid; t < NP * NH; t += 256) {
            int p = t >> 5, h = t & 31;
            g_wbg[t] = Wb[h * NP + p] * pg[p];             // [p][h]
        }
    } else {
        if (tid < NH) {
            int h = tid;
            float s1 = 0.f, s2 = 0.f;
            for (int p = 0; p < NP; p++) {
                float wv = Wb[h * NP + p];
                s1 += wv * pg[p];
                s2 += wv * pb[p];
            }
            g_c1[h] = s1;
            g_c2[h] = s2 + bb[h];
        }
    }
}

// ---------------- layernorm over E=512, one row per block (128 threads) ----------------
__global__ void ln_kernel(const float* __restrict__ q, const float* __restrict__ g,
                          const float* __restrict__ b)
{
    int row = blockIdx.x;
    int tid = threadIdx.x;
    const float* x = q + (size_t)row * NE;
    float4 v = *(const float4*)(x + tid * 4);
    float s  = v.x + v.y + v.z + v.w;
    float ss = v.x * v.x + v.y * v.y + v.z * v.z + v.w * v.w;
#pragma unroll
    for (int o = 16; o; o >>= 1) {
        s  += __shfl_xor_sync(0xffffffffu, s, o);
        ss += __shfl_xor_sync(0xffffffffu, ss, o);
    }
    __shared__ float rs[4], rss[4];
    int w = tid >> 5;
    if ((tid & 31) == 0) { rs[w] = s; rss[w] = ss; }
    __syncthreads();
    s  = rs[0] + rs[1] + rs[2] + rs[3];
    ss = rss[0] + rss[1] + rss[2] + rss[3];
    float mu   = s * (1.f / 512.f);
    float var  = ss * (1.f / 512.f) - mu * mu;
    float rstd = rsqrtf(var + 1e-5f);
    float4 gg = *(const float4*)(g + tid * 4);
    float4 bv = *(const float4*)(b + tid * 4);
    float4 o;
    o.x = (v.x - mu) * rstd * gg.x + bv.x;
    o.y = (v.y - mu) * rstd * gg.y + bv.y;
    o.z = (v.z - mu) * rstd * gg.z + bv.z;
    o.w = (v.w - mu) * rstd * gg.w + bv.w;
    *(float4*)(g_xn + (size_t)row * NE + tid * 4) = o;
}

// ---------------- GEMM: C[2048][1088] = xn[2048][512] @ Wcat[1088][512]^T ----------------
__global__ __launch_bounds__(256) void gemm_qkw_kernel()
{
    __shared__ float As[16][68];
    __shared__ float Bs[16][68];
    int m0 = blockIdx.x * 64, n0 = blockIdx.y * 64;
    int tid = threadIdx.x;
    int tm = tid >> 4, tn = tid & 15;
    int lr = tid >> 2, lc = tid & 3;
    float acc[4][4] = {};
    for (int k0 = 0; k0 < NE; k0 += 16) {
        float4 av = *(const float4*)&g_xn[(size_t)(m0 + lr) * NE + k0 + lc * 4];
        float4 bv = *(const float4*)&g_Wcat[(size_t)(n0 + lr) * NE + k0 + lc * 4];
        As[lc * 4 + 0][lr] = av.x; As[lc * 4 + 1][lr] = av.y;
        As[lc * 4 + 2][lr] = av.z; As[lc * 4 + 3][lr] = av.w;
        Bs[lc * 4 + 0][lr] = bv.x; Bs[lc * 4 + 1][lr] = bv.y;
        Bs[lc * 4 + 2][lr] = bv.z; Bs[lc * 4 + 3][lr] = bv.w;
        __syncthreads();
#pragma unroll
        for (int k = 0; k < 16; k++) {
            float4 a = *(const float4*)&As[k][tm * 4];
            float4 b = *(const float4*)&Bs[k][tn * 4];
            acc[0][0] += a.x * b.x; acc[0][1] += a.x * b.y; acc[0][2] += a.x * b.z; acc[0][3] += a.x * b.w;
            acc[1][0] += a.y * b.x; acc[1][1] += a.y * b.y; acc[1][2] += a.y * b.z; acc[1][3] += a.y * b.w;
            acc[2][0] += a.z * b.x; acc[2][1] += a.z * b.y; acc[2][2] += a.z * b.z; acc[2][3] += a.z * b.w;
            acc[3][0] += a.w * b.x; acc[3][1] += a.w * b.y; acc[3][2] += a.w * b.z; acc[3][3] += a.w * b.w;
        }
        __syncthreads();
    }
#pragma unroll
    for (int t = 0; t < 4; t++)
#pragma unroll
        for (int u = 0; u < 4; u++)
            g_C[(size_t)(m0 + tm * 4 + t) * CW + n0 + tn * 4 + u] = acc[t][u];
}

// ---------------- fused attention kernel v2: one CTA per (b, i) ----------------
// Flash-style online softmax, logits never materialized.
// Thread (jg=tid>>3, hg=tid&7) owns j = tile*64 + jg*2 + {0,1}, h = hg*4 + {0..3}.
// smem (floats): pair_s 64*132=8448 | wbg_s 4096 | q_s 512 | mu_s 64 | rs_s 64 | mrg 8*32*5=1280
#define SM_FLOATS (8448 + 4096 + 512 + 64 + 64 + 1280)

__global__ __launch_bounds__(256, 2) void fused_attn_kernel(
    const float* __restrict__ pair, const float* __restrict__ mask,
    const float* __restrict__ dpos, float* __restrict__ out)
{
    extern __shared__ float sm[];
    float* pair_s = sm;                        // [64][132]
    float* wbg_s  = pair_s + 64 * 132;         // [128][32]
    float* q_s    = wbg_s + 128 * 32;          // [512]
    float* mu_s   = q_s + 512;                 // [64]
    float* rs_s   = mu_s + 64;                 // [64]
    float* mrg    = rs_s + 64;                 // [8][32][5]  (m,z,a0,a1,a2)

    int bi = blockIdx.x;                       // b*512 + i
    int b = bi >> 9, i = bi & 511;
    int tid = threadIdx.x;
    int jg = tid >> 3, hg = tid & 7;
    int hg4 = hg * 4;

    // stage q row + wbg + per-head constants
    const float* crow = g_C + (size_t)bi * CW;
    for (int e = tid; e < 512; e += 256) q_s[e] = crow[e];
    for (int t = tid; t < NP * NH; t += 256) wbg_s[t] = g_wbg[t];
    float4 c1v = *(const float4*)&g_c1[hg4];
    float4 c2v = *(const float4*)&g_c2[hg4];
    float c1a[4] = { c1v.x, c1v.y, c1v.z, c1v.w };
    float c2a[4] = { c2v.x, c2v.y, c2v.z, c2v.w };

    // online-softmax state per owned head u
    float m_r[4] = { -1e30f, -1e30f, -1e30f, -1e30f };
    float z_r[4] = { 0.f, 0.f, 0.f, 0.f };
    float a0_r[4] = {}, a1_r[4] = {}, a2_r[4] = {};

    const float* pbase = pair + (size_t)bi * NN * NP;   // pair[b,i,:,:]
    const float4* wbg_v = (const float4*)wbg_s;

    for (int tile = 0; tile < NTILE; ++tile) {
        int j0 = tile * JT;
        __syncthreads();
        // ---- stage pair tile: 64 rows x 32 float4 ----
#pragma unroll
        for (int it = 0; it < 8; ++it) {
            int idx = it * 256 + tid;
            int jl = idx >> 5, p4 = idx & 31;
            float4 v = *(const float4*)(pbase + (size_t)(j0 + jl) * NP + p4 * 4);
            *(float4*)&pair_s[jl * 132 + p4 * 4] = v;
        }
        __syncthreads();
        // ---- per-row LN stats (interleaved p to stay bank-conflict-free) ----
        {
            int row = tid >> 2, qtr = tid & 3;
            const float* pr = &pair_s[row * 132 + qtr];
            float s = 0.f, ss = 0.f;
#pragma unroll
            for (int k = 0; k < 32; k++) { float v = pr[4 * k]; s += v; ss += v * v; }
            s  += __shfl_xor_sync(0xffffffffu, s, 1);
            ss += __shfl_xor_sync(0xffffffffu, ss, 1);
            s  += __shfl_xor_sync(0xffffffffu, s, 2);
            ss += __shfl_xor_sync(0xffffffffu, ss, 2);
            if (qtr == 0) {
                float mu  = s * (1.f / 128.f);
                float var = ss * (1.f / 128.f) - mu * mu;
                mu_s[row] = mu;
                rs_s[row] = rsqrtf(var + 1e-5f);
            }
        }
        __syncthreads();
        // ---- bias GEMM: 2j x 4h register tile, K=128, float4 LDS ----
        float acc[2][4] = {};
        const float4* pr0 = (const float4*)&pair_s[(jg * 2 + 0) * 132];
        const float4* pr1 = (const float4*)&pair_s[(jg * 2 + 1) * 132];
#pragma unroll 4
        for (int p4 = 0; p4 < 32; ++p4) {
            float4 a0 = pr0[p4];
            float4 a1 = pr1[p4];
            float4 w0 = wbg_v[(p4 * 4 + 0) * 8 + hg];
            float4 w1 = wbg_v[(p4 * 4 + 1) * 8 + hg];
            float4 w2 = wbg_v[(p4 * 4 + 2) * 8 + hg];
            float4 w3 = wbg_v[(p4 * 4 + 3) * 8 + hg];
            acc[0][0] += a0.x * w0.x; acc[0][1] += a0.x * w0.y; acc[0][2] += a0.x * w0.z; acc[0][3] += a0.x * w0.w;
            acc[1][0] += a1.x * w0.x; acc[1][1] += a1.x * w0.y; acc[1][2] += a1.x * w0.z; acc[1][3] += a1.x * w0.w;
            acc[0][0] += a0.y * w1.x; acc[0][1] += a0.y * w1.y; acc[0][2] += a0.y * w1.z; acc[0][3] += a0.y * w1.w;
            acc[1][0] += a1.y * w1.x; acc[1][1] += a1.y * w1.y; acc[1][2] += a1.y * w1.z; acc[1][3] += a1.y * w1.w;
            acc[0][0] += a0.z * w2.x; acc[0][1] += a0.z * w2.y; acc[0][2] += a0.z * w2.z; acc[0][3] += a0.z * w2.w;
            acc[1][0] += a1.z * w2.x; acc[1][1] += a1.z * w2.y; acc[1][2] += a1.z * w2.z; acc[1][3] += a1.z * w2.w;
            acc[0][0] += a0.w * w3.x; acc[0][1] += a0.w * w3.y; acc[0][2] += a0.w * w3.z; acc[0][3] += a0.w * w3.w;
            acc[1][0] += a1.w * w3.x; acc[1][1] += a1.w * w3.y; acc[1][2] += a1.w * w3.z; acc[1][3] += a1.w * w3.w;
        }
        // ---- epilogue per owned j: finish LN bias, qk, mask; online softmax + force accum ----
#pragma unroll
        for (int t = 0; t < 2; t++) {
            int jl = jg * 2 + t;
            int j  = j0 + jl;
            float muv = mu_s[jl], rsv = rs_s[jl];
            const float* krow = g_C + ((size_t)(b * NN + j)) * CW + 512;
            float4 w4 = *(const float4*)(g_C + ((size_t)(b * NN + j)) * CW + 1024 + hg4);
            float wr[4] = { w4.x, w4.y, w4.z, w4.w };
            const float* dp = dpos + ((size_t)bi * NN + j) * 3;
            float dp0 = dp[0], dp1 = dp[1], dp2 = dp[2];
            const float* mrow = mask + (((size_t)(b * NH) * NN + i) * NN) + j;  // + h*NN*NN below
#pragma unroll
            for (int u = 0; u < 4; u++) {
                int h = hg4 + u;
                // qk dot (16 d)
                float qk = 0.f;
#pragma unroll
                for (int d = 0; d < ND; d += 4) {
                    float4 kv = *(const float4*)(krow + h * ND + d);
                    float4 qv = *(const float4*)&q_s[h * ND + d];
                    qk += kv.x * qv.x + kv.y * qv.y + kv.z * qv.z + kv.w * qv.w;
                }
                float mk = mrow[(size_t)h * NN * NN];
                float lv = rsv * (acc[t][u] - muv * c1a[u]) + c2a[u] + qk + mk;
                // online softmax update
                float nm = fmaxf(m_r[u], lv);
                float sc = __expf(m_r[u] - nm);
                float e  = __expf(lv - nm);
                m_r[u] = nm;
                z_r[u] = z_r[u] * sc + e;
                float ew = e * wr[u];
                a0_r[u] = a0_r[u] * sc + ew * dp0;
                a1_r[u] = a1_r[u] * sc + ew * dp1;
                a2_r[u] = a2_r[u] * sc + ew * dp2;
            }
        }
    }

    // ---- flash merge across the 32 threads sharing each head ----
    // lanes with same hg: {hg, hg+8, hg+16, hg+24} -> shfl_xor 8, 16
#pragma unroll
    for (int u = 0; u < 4; u++) {
#pragma unroll
        for (int off = 8; off <= 16; off <<= 1) {
            float om = __shfl_xor_sync(0xffffffffu, m_r[u], off);
            float oz = __shfl_xor_sync(0xffffffffu, z_r[u], off);
            float o0 = __shfl_xor_sync(0xffffffffu, a0_r[u], off);
            float o1 = __shfl_xor_sync(0xffffffffu, a1_r[u], off);
            float o2 = __shfl_xor_sync(0xffffffffu, a2_r[u], off);
            float M = fmaxf(m_r[u], om);
            float s1 = __expf(m_r[u] - M);
            float s2 = __expf(om - M);
            z_r[u]  = z_r[u]  * s1 + oz * s2;
            a0_r[u] = a0_r[u] * s1 + o0 * s2;
            a1_r[u] = a1_r[u] * s1 + o1 * s2;
            a2_r[u] = a2_r[u] * s1 + o2 * s2;
            m_r[u] = M;
        }
    }
    __syncthreads();   // pair_s phase done; mrg region safe
    {
        int w = tid >> 5, lane = tid & 31;
        if (lane < 8) {   // lane == hg representative
#pragma unroll
            for (int u = 0; u < 4; u++) {
                int h = lane * 4 + u;
                float* e = &mrg[(w * 32 + h) * 5];
                e[0] = m_r[u]; e[1] = z_r[u]; e[2] = a0_r[u]; e[3] = a1_r[u]; e[4] = a2_r[u];
            }
        }
    }
    __syncthreads();
    if (tid < 32) {
        int h = tid;
        float M = -1e30f, Z = 0.f, A0 = 0.f, A1 = 0.f, A2 = 0.f;
#pragma unroll
        for (int w = 0; w < 8; w++) {
            const float* e = &mrg[(w * 32 + h) * 5];
            float om = e[0];
            float nM = fmaxf(M, om);
            float s1 = __expf(M - nM);
            float s2 = __expf(om - nM);
            Z  = Z * s1 + e[1] * s2;
            A0 = A0 * s1 + e[2] * s2;
            A1 = A1 * s1 + e[3] * s2;
            A2 = A2 * s1 + e[4] * s2;
            M = nM;
        }
        float inv = 1.f / Z;
        float f0 = A0 * inv, f1 = A1 * inv, f2 = A2 * inv;
#pragma unroll
        for (int o = 16; o; o >>= 1) {
            f0 += __shfl_xor_sync(0xffffffffu, f0, o);
            f1 += __shfl_xor_sync(0xffffffffu, f1, o);
            f2 += __shfl_xor_sync(0xffffffffu, f2, o);
        }
        if (tid == 0) {
            out[(size_t)bi * 3 + 0] = f0;
            out[(size_t)bi * 3 + 1] = f1;
            out[(size_t)bi * 3 + 2] = f2;
        }
    }
}

// ---------------- launcher ----------------
extern "C" void kernel_launch(void* const* d_in, const int* in_sizes, int n_in,
                              void* d_out, int out_size)
{
    (void)in_sizes; (void)n_in; (void)out_size;
    const float* query  = (const float*)d_in[0];
    const float* pair   = (const float*)d_in[1];
    const float* mask   = (const float*)d_in[2];
    const float* dpos   = (const float*)d_in[3];
    const float* ln_g   = (const float*)d_in[4];
    const float* ln_b   = (const float*)d_in[5];
    const float* Wq     = (const float*)d_in[6];
    const float* Wk     = (const float*)d_in[7];
    const float* Wv     = (const float*)d_in[8];
    const float* pln_g  = (const float*)d_in[9];
    const float* pln_b  = (const float*)d_in[10];
    const float* Wb     = (const float*)d_in[11];
    const float* bb     = (const float*)d_in[12];
    const float* Wf     = (const float*)d_in[13];
    float* out = (float*)d_out;

    static_assert(SM_FLOATS * 4 <= 100 * 1024, "smem budget for 2 CTAs/SM");
    cudaFuncSetAttribute(fused_attn_kernel,
                         cudaFuncAttributeMaxDynamicSharedMemorySize, SM_FLOATS * 4);

    prep_kernel<<<1090, 256>>>(Wq, Wk, Wv, Wf, Wb, bb, pln_g, pln_b);
    ln_kernel<<<NB * NN, 128>>>(query, ln_g, ln_b);
    gemm_qkw_kernel<<<dim3(32, 17), 256>>>();
    fused_attn_kernel<<<NB * NN, 256, SM_FLOATS * 4>>>(pair, mask, dpos, out);
}

// round 3
// speedup vs baseline: 1.7711x; 1.3018x over previous
#include <cuda_runtime.h>
#include <cstddef>

#define NB 4
#define NN 512
#define NE 512
#define NH 32
#define ND 16
#define NP 128
#define CW 1088          // scratch C width: [q 512 | k 512 | w 32 | pad 32]
#define JT 64            // j-tile in fused kernel
#define NTILE (NN / JT)  // 8

// ---------------- device scratch (no allocations allowed) ----------------
__device__ float g_xn[NB * NN * NE];        // layernormed query, 4 MB
__device__ float g_Wcat[CW * NE];           // concatenated weights, 2.2 MB
__device__ float g_C[NB * NN * CW];         // q|k|w per token, 8.9 MB
__device__ float g_wbg2[NP * NH];           // Wb*pln_g, pair-interleaved [p/2][h][2]
__device__ float g_c1[NH];
__device__ float g_c2[NH];
__device__ float g_qkm[(size_t)NB * NH * NN * NN];   // qk + mask, 134 MB

__device__ __forceinline__ void ffma2(unsigned long long& d, unsigned long long a, unsigned long long b) {
    asm("fma.rn.f32x2 %0, %1, %2, %0;" : "+l"(d) : "l"(a), "l"(b));
}
__device__ __forceinline__ void unpack2(float& lo, float& hi, unsigned long long v) {
    asm("mov.b64 {%0, %1}, %2;" : "=f"(lo), "=f"(hi) : "l"(v));
}

// ---------------- prep: build Wcat, wbg2, c1, c2 ----------------
__global__ void prep_kernel(const float* __restrict__ Wq, const float* __restrict__ Wk,
                            const float* __restrict__ Wv, const float* __restrict__ Wf,
                            const float* __restrict__ Wb, const float* __restrict__ bb,
                            const float* __restrict__ pg, const float* __restrict__ pb)
{
    int r = blockIdx.x;
    int tid = threadIdx.x;
    if (r < 512) {
        for (int e = tid; e < NE; e += 256)
            g_Wcat[r * NE + e] = Wq[r * NE + e] * 0.25f;   // SCALING folded in
    } else if (r < 1024) {
        int rr = r - 512;
        for (int e = tid; e < NE; e += 256)
            g_Wcat[r * NE + e] = Wk[rr * NE + e];
    } else if (r < 1056) {
        int h = r - 1024;
        for (int e = tid; e < NE; e += 256) {
            float s = 0.f;
#pragma unroll
            for (int d = 0; d < ND; d++)
                s += Wf[h * ND + d] * Wv[(h * ND + d) * NE + e];
            g_Wcat[r * NE + e] = s;                        // Wvf
        }
    } else if (r < 1088) {
        for (int e = tid; e < NE; e += 256) g_Wcat[r * NE + e] = 0.f;
    } else if (r == 1088) {
        for (int t = tid; t < NP * NH; t += 256) {
            int p = t >> 5, h = t & 31;
            // pair-interleaved layout: [p/2][h][2]
            g_wbg2[(p >> 1) * 64 + h * 2 + (p & 1)] = Wb[h * NP + p] * pg[p];
        }
    } else {
        if (tid < NH) {
            int h = tid;
            float s1 = 0.f, s2 = 0.f;
            for (int p = 0; p < NP; p++) {
                float wv = Wb[h * NP + p];
                s1 += wv * pg[p];
                s2 += wv * pb[p];
            }
            g_c1[h] = s1;
            g_c2[h] = s2 + bb[h];
        }
    }
}

// ---------------- layernorm over E=512, one row per block ----------------
__global__ void ln_kernel(const float* __restrict__ q, const float* __restrict__ g,
                          const float* __restrict__ b)
{
    int row = blockIdx.x;
    int tid = threadIdx.x;
    const float* x = q + (size_t)row * NE;
    float4 v = *(const float4*)(x + tid * 4);
    float s  = v.x + v.y + v.z + v.w;
    float ss = v.x * v.x + v.y * v.y + v.z * v.z + v.w * v.w;
#pragma unroll
    for (int o = 16; o; o >>= 1) {
        s  += __shfl_xor_sync(0xffffffffu, s, o);
        ss += __shfl_xor_sync(0xffffffffu, ss, o);
    }
    __shared__ float rs[4], rss[4];
    int w = tid >> 5;
    if ((tid & 31) == 0) { rs[w] = s; rss[w] = ss; }
    __syncthreads();
    s  = rs[0] + rs[1] + rs[2] + rs[3];
    ss = rss[0] + rss[1] + rss[2] + rss[3];
    float mu   = s * (1.f / 512.f);
    float var  = ss * (1.f / 512.f) - mu * mu;
    float rstd = rsqrtf(var + 1e-5f);
    float4 gg = *(const float4*)(g + tid * 4);
    float4 bv = *(const float4*)(b + tid * 4);
    float4 o;
    o.x = (v.x - mu) * rstd * gg.x + bv.x;
    o.y = (v.y - mu) * rstd * gg.y + bv.y;
    o.z = (v.z - mu) * rstd * gg.z + bv.z;
    o.w = (v.w - mu) * rstd * gg.w + bv.w;
    *(float4*)(g_xn + (size_t)row * NE + tid * 4) = o;
}

// ---------------- GEMM: C[2048][1088] = xn @ Wcat^T ----------------
__global__ __launch_bounds__(256) void gemm_qkw_kernel()
{
    __shared__ float As[16][68];
    __shared__ float Bs[16][68];
    int m0 = blockIdx.x * 64, n0 = blockIdx.y * 64;
    int tid = threadIdx.x;
    int tm = tid >> 4, tn = tid & 15;
    int lr = tid >> 2, lc = tid & 3;
    float acc[4][4] = {};
    for (int k0 = 0; k0 < NE; k0 += 16) {
        float4 av = *(const float4*)&g_xn[(size_t)(m0 + lr) * NE + k0 + lc * 4];
        float4 bv = *(const float4*)&g_Wcat[(size_t)(n0 + lr) * NE + k0 + lc * 4];
        As[lc * 4 + 0][lr] = av.x; As[lc * 4 + 1][lr] = av.y;
        As[lc * 4 + 2][lr] = av.z; As[lc * 4 + 3][lr] = av.w;
        Bs[lc * 4 + 0][lr] = bv.x; Bs[lc * 4 + 1][lr] = bv.y;
        Bs[lc * 4 + 2][lr] = bv.z; Bs[lc * 4 + 3][lr] = bv.w;
        __syncthreads();
#pragma unroll
        for (int k = 0; k < 16; k++) {
            float4 a = *(const float4*)&As[k][tm * 4];
            float4 b = *(const float4*)&Bs[k][tn * 4];
            acc[0][0] += a.x * b.x; acc[0][1] += a.x * b.y; acc[0][2] += a.x * b.z; acc[0][3] += a.x * b.w;
            acc[1][0] += a.y * b.x; acc[1][1] += a.y * b.y; acc[1][2] += a.y * b.z; acc[1][3] += a.y * b.w;
            acc[2][0] += a.z * b.x; acc[2][1] += a.z * b.y; acc[2][2] += a.z * b.z; acc[2][3] += a.z * b.w;
            acc[3][0] += a.w * b.x; acc[3][1] += a.w * b.y; acc[3][2] += a.w * b.z; acc[3][3] += a.w * b.w;
        }
        __syncthreads();
    }
#pragma unroll
    for (int t = 0; t < 4; t++)
#pragma unroll
        for (int u = 0; u < 4; u++)
            g_C[(size_t)(m0 + tm * 4 + t) * CW + n0 + tn * 4 + u] = acc[t][u];
}

// ---------------- qk+mask kernel: g_qkm[b][h][i][j] = q(b,i,h)·k(b,j,h) + mask ----------------
// grid (j-half, h, b), 256 threads; thread owns j = jhalf*256 + tid, k in registers.
__global__ __launch_bounds__(256) void qk_kernel(const float* __restrict__ mask)
{
    __shared__ float qs[NN * ND];   // 32 KB: q[i][d] for all i, this head
    int jhalf = blockIdx.x, h = blockIdx.y, b = blockIdx.z;
    int tid = threadIdx.x;
    int j = jhalf * 256 + tid;

    // stage q for all i (head h)
    for (int idx = tid; idx < NN * 4; idx += 256) {
        int i = idx >> 2, d4 = idx & 3;
        float4 v = *(const float4*)&g_C[(size_t)(b * NN + i) * CW + h * ND + d4 * 4];
        *(float4*)&qs[i * ND + d4 * 4] = v;
    }
    // k row for this thread's j, registers
    const float* kr = g_C + (size_t)(b * NN + j) * CW + 512 + h * ND;
    float4 k0 = *(const float4*)(kr + 0);
    float4 k1 = *(const float4*)(kr + 4);
    float4 k2 = *(const float4*)(kr + 8);
    float4 k3 = *(const float4*)(kr + 12);
    __syncthreads();

    size_t base = (((size_t)b * NH + h) * NN) * NN + j;
    const float* mrow = mask + base;
    float* orow = g_qkm + base;
    for (int i = 0; i < NN; i++) {
        const float* q = &qs[i * ND];
        float4 q0 = *(const float4*)(q + 0);
        float4 q1 = *(const float4*)(q + 4);
        float4 q2 = *(const float4*)(q + 8);
        float4 q3 = *(const float4*)(q + 12);
        float d =
            q0.x * k0.x + q0.y * k0.y + q0.z * k0.z + q0.w * k0.w +
            q1.x * k1.x + q1.y * k1.y + q1.z * k1.z + q1.w * k1.w +
            q2.x * k2.x + q2.y * k2.y + q2.z * k2.z + q2.w * k2.w +
            q3.x * k3.x + q3.y * k3.y + q3.z * k3.z + q3.w * k3.w;
        orow[(size_t)i * NN] = d + mrow[(size_t)i * NN];
    }
}

// ---------------- fused attention kernel v3 ----------------
// CTA per (b,i). Flash online softmax. qkm staged per tile; bias GEMM in f32x2.
// smem: pair_s 64*132 | wbg2_s 4096 | qkm_s 32*68 | mu 64 | rs 64 | mrg 1280
#define SM_FLOATS (64 * 132 + 4096 + 32 * 68 + 64 + 64 + 1280)

__global__ __launch_bounds__(256, 2) void fused_attn_kernel(
    const float* __restrict__ pair, const float* __restrict__ dpos,
    float* __restrict__ out)
{
    extern __shared__ float sm[];
    float* pair_s = sm;                        // [64][132]
    float* wbg2_s = pair_s + 64 * 132;         // [p/2][32][2]
    float* qkm_s  = wbg2_s + 4096;             // [32][68]
    float* mu_s   = qkm_s + 32 * 68;           // [64]
    float* rs_s   = mu_s + 64;                 // [64]
    float* mrg    = rs_s + 64;                 // [8][32][5]

    int bi = blockIdx.x;                       // b*512 + i
    int b = bi >> 9, i = bi & 511;
    int tid = threadIdx.x;
    int jg = tid >> 3, hg = tid & 7;
    int hg4 = hg * 4;

    for (int t = tid; t < NP * NH; t += 256) wbg2_s[t] = g_wbg2[t];
    float4 c1v = *(const float4*)&g_c1[hg4];
    float4 c2v = *(const float4*)&g_c2[hg4];
    float c1a[4] = { c1v.x, c1v.y, c1v.z, c1v.w };
    float c2a[4] = { c2v.x, c2v.y, c2v.z, c2v.w };

    float m_r[4] = { -1e30f, -1e30f, -1e30f, -1e30f };
    float z_r[4] = { 0.f, 0.f, 0.f, 0.f };
    float a0_r[4] = {}, a1_r[4] = {}, a2_r[4] = {};

    const float* pbase = pair + (size_t)bi * NN * NP;
    const float* qkbase = g_qkm + ((size_t)b * NH * NN + i) * NN;  // + h*NN*NN + j

    for (int tile = 0; tile < NTILE; ++tile) {
        int j0 = tile * JT;
        __syncthreads();
        // ---- stage pair tile; warp w loads row it*8+w; fused LN stats ----
#pragma unroll
        for (int it = 0; it < 8; ++it) {
            int idx = it * 256 + tid;
            int jl = idx >> 5, p4 = idx & 31;
            float4 v = *(const float4*)(pbase + (size_t)(j0 + jl) * NP + p4 * 4);
            *(float4*)&pair_s[jl * 132 + p4 * 4] = v;
            float s  = v.x + v.y + v.z + v.w;
            float ss = v.x * v.x + v.y * v.y + v.z * v.z + v.w * v.w;
#pragma unroll
            for (int o = 16; o; o >>= 1) {
                s  += __shfl_xor_sync(0xffffffffu, s, o);
                ss += __shfl_xor_sync(0xffffffffu, ss, o);
            }
            if ((tid & 31) == 0) {
                float mu  = s * (1.f / 128.f);
                float var = ss * (1.f / 128.f) - mu * mu;
                mu_s[jl] = mu;
                rs_s[jl] = rsqrtf(var + 1e-5f);
            }
        }
        // ---- stage qkm tile [32h][64j] (coalesced per h-row) ----
#pragma unroll
        for (int it = 0; it < 2; ++it) {
            int idx = it * 256 + tid;
            int h = idx >> 4, j4 = idx & 15;
            float4 v = *(const float4*)(qkbase + (size_t)h * NN * NN + j0 + j4 * 4);
            *(float4*)&qkm_s[h * 68 + j4 * 4] = v;
        }
        __syncthreads();
        // ---- bias GEMM in f32x2: 2j x 4h, K=128 as 64 p-pairs ----
        unsigned long long acc2[2][4] = {};
        const ulonglong2* pa0 = (const ulonglong2*)&pair_s[(jg * 2 + 0) * 132];
        const ulonglong2* pa1 = (const ulonglong2*)&pair_s[(jg * 2 + 1) * 132];
        const unsigned long long* wb = (const unsigned long long*)wbg2_s;  // [p2][32h]
#pragma unroll 8
        for (int p4 = 0; p4 < 32; ++p4) {
            ulonglong2 a0 = pa0[p4];          // (p0,p1) (p2,p3) row jg*2
            ulonglong2 a1 = pa1[p4];
            int p2 = p4 * 2;
            ulonglong2 wA0 = *(const ulonglong2*)&wb[(size_t)(p2 + 0) * 32 + hg4];
            ulonglong2 wB0 = *(const ulonglong2*)&wb[(size_t)(p2 + 0) * 32 + hg4 + 2];
            ulonglong2 wA1 = *(const ulonglong2*)&wb[(size_t)(p2 + 1) * 32 + hg4];
            ulonglong2 wB1 = *(const ulonglong2*)&wb[(size_t)(p2 + 1) * 32 + hg4 + 2];
            ffma2(acc2[0][0], a0.x, wA0.x); ffma2(acc2[0][1], a0.x, wA0.y);
            ffma2(acc2[0][2], a0.x, wB0.x); ffma2(acc2[0][3], a0.x, wB0.y);
            ffma2(acc2[1][0], a1.x, wA0.x); ffma2(acc2[1][1], a1.x, wA0.y);
            ffma2(acc2[1][2], a1.x, wB0.x); ffma2(acc2[1][3], a1.x, wB0.y);
            ffma2(acc2[0][0], a0.y, wA1.x); ffma2(acc2[0][1], a0.y, wA1.y);
            ffma2(acc2[0][2], a0.y, wB1.x); ffma2(acc2[0][3], a0.y, wB1.y);
            ffma2(acc2[1][0], a1.y, wA1.x); ffma2(acc2[1][1], a1.y, wA1.y);
            ffma2(acc2[1][2], a1.y, wB1.x); ffma2(acc2[1][3], a1.y, wB1.y);
        }
        // ---- epilogue: affine LN bias + qkm; online softmax + force accum ----
#pragma unroll
        for (int t = 0; t < 2; t++) {
            int jl = jg * 2 + t;
            int j  = j0 + jl;
            float muv = mu_s[jl], rsv = rs_s[jl];
            float4 w4 = *(const float4*)(g_C + ((size_t)(b * NN + j)) * CW + 1024 + hg4);
            float wr[4] = { w4.x, w4.y, w4.z, w4.w };
            const float* dp = dpos + ((size_t)bi * NN + j) * 3;
            float dp0 = dp[0], dp1 = dp[1], dp2 = dp[2];
            float accf[4];
            {
                float lo, hi;
                unpack2(lo, hi, acc2[t][0]); accf[0] = lo + hi;
                unpack2(lo, hi, acc2[t][1]); accf[1] = lo + hi;
                unpack2(lo, hi, acc2[t][2]); accf[2] = lo + hi;
                unpack2(lo, hi, acc2[t][3]); accf[3] = lo + hi;
            }
#pragma unroll
            for (int u = 0; u < 4; u++) {
                int h = hg4 + u;
                float qkm = qkm_s[h * 68 + jl];
                float lv = rsv * (accf[u] - muv * c1a[u]) + c2a[u] + qkm;
                float nm = fmaxf(m_r[u], lv);
                float sc = __expf(m_r[u] - nm);
                float e  = __expf(lv - nm);
                m_r[u] = nm;
                z_r[u] = z_r[u] * sc + e;
                float ew = e * wr[u];
                a0_r[u] = a0_r[u] * sc + ew * dp0;
                a1_r[u] = a1_r[u] * sc + ew * dp1;
                a2_r[u] = a2_r[u] * sc + ew * dp2;
            }
        }
    }

    // ---- flash merge across 32 threads sharing each head (shfl 8,16) ----
#pragma unroll
    for (int u = 0; u < 4; u++) {
#pragma unroll
        for (int off = 8; off <= 16; off <<= 1) {
            float om = __shfl_xor_sync(0xffffffffu, m_r[u], off);
            float oz = __shfl_xor_sync(0xffffffffu, z_r[u], off);
            float o0 = __shfl_xor_sync(0xffffffffu, a0_r[u], off);
            float o1 = __shfl_xor_sync(0xffffffffu, a1_r[u], off);
            float o2 = __shfl_xor_sync(0xffffffffu, a2_r[u], off);
            float M = fmaxf(m_r[u], om);
            float s1 = __expf(m_r[u] - M);
            float s2 = __expf(om - M);
            z_r[u]  = z_r[u]  * s1 + oz * s2;
            a0_r[u] = a0_r[u] * s1 + o0 * s2;
            a1_r[u] = a1_r[u] * s1 + o1 * s2;
            a2_r[u] = a2_r[u] * s1 + o2 * s2;
            m_r[u] = M;
        }
    }
    __syncthreads();
    {
        int w = tid >> 5, lane = tid & 31;
        if (lane < 8) {
#pragma unroll
            for (int u = 0; u < 4; u++) {
                int h = lane * 4 + u;
                float* e = &mrg[(w * 32 + h) * 5];
                e[0] = m_r[u]; e[1] = z_r[u]; e[2] = a0_r[u]; e[3] = a1_r[u]; e[4] = a2_r[u];
            }
        }
    }
    __syncthreads();
    if (tid < 32) {
        int h = tid;
        float M = -1e30f, Z = 0.f, A0 = 0.f, A1 = 0.f, A2 = 0.f;
#pragma unroll
        for (int w = 0; w < 8; w++) {
            const float* e = &mrg[(w * 32 + h) * 5];
            float om = e[0];
            float nM = fmaxf(M, om);
            float s1 = __expf(M - nM);
            float s2 = __expf(om - nM);
            Z  = Z * s1 + e[1] * s2;
            A0 = A0 * s1 + e[2] * s2;
            A1 = A1 * s1 + e[3] * s2;
            A2 = A2 * s1 + e[4] * s2;
            M = nM;
        }
        float inv = 1.f / Z;
        float f0 = A0 * inv, f1 = A1 * inv, f2 = A2 * inv;
#pragma unroll
        for (int o = 16; o; o >>= 1) {
            f0 += __shfl_xor_sync(0xffffffffu, f0, o);
            f1 += __shfl_xor_sync(0xffffffffu, f1, o);
            f2 += __shfl_xor_sync(0xffffffffu, f2, o);
        }
        if (tid == 0) {
            out[(size_t)bi * 3 + 0] = f0;
            out[(size_t)bi * 3 + 1] = f1;
            out[(size_t)bi * 3 + 2] = f2;
        }
    }
}

// ---------------- launcher ----------------
extern "C" void kernel_launch(void* const* d_in, const int* in_sizes, int n_in,
                              void* d_out, int out_size)
{
    (void)in_sizes; (void)n_in; (void)out_size;
    const float* query  = (const float*)d_in[0];
    const float* pair   = (const float*)d_in[1];
    const float* mask   = (const float*)d_in[2];
    const float* dpos   = (const float*)d_in[3];
    const float* ln_g   = (const float*)d_in[4];
    const float* ln_b   = (const float*)d_in[5];
    const float* Wq     = (const float*)d_in[6];
    const float* Wk     = (const float*)d_in[7];
    const float* Wv     = (const float*)d_in[8];
    const float* pln_g  = (const float*)d_in[9];
    const float* pln_b  = (const float*)d_in[10];
    const float* Wb     = (const float*)d_in[11];
    const float* bb     = (const float*)d_in[12];
    const float* Wf     = (const float*)d_in[13];
    float* out = (float*)d_out;

    static_assert(SM_FLOATS * 4 <= 100 * 1024, "smem budget for 2 CTAs/SM");
    cudaFuncSetAttribute(fused_attn_kernel,
                         cudaFuncAttributeMaxDynamicSharedMemorySize, SM_FLOATS * 4);

    prep_kernel<<<1090, 256>>>(Wq, Wk, Wv, Wf, Wb, bb, pln_g, pln_b);
    ln_kernel<<<NB * NN, 128>>>(query, ln_g, ln_b);
    gemm_qkw_kernel<<<dim3(32, 17), 256>>>();
    qk_kernel<<<dim3(2, NH, NB), 256>>>(mask);
    fused_attn_kernel<<<NB * NN, 256, SM_FLOATS * 4>>>(pair, dpos, out);
}

// round 4
// speedup vs baseline: 2.0525x; 1.1589x over previous
#include <cuda_runtime.h>
#include <cstddef>

#define NB 4
#define NN 512
#define NE 512
#define NH 32
#define ND 16
#define NP 128
#define CW 1088          // scratch C width: [q 512 | k 512 | w 32 | pad 32]
#define JT 64            // j-tile in fused kernel
#define NTILE (NN / JT)  // 8

// ---------------- device scratch (no allocations allowed) ----------------
__device__ float g_xn[NB * NN * NE];        // layernormed query, 4 MB
__device__ float g_Wcat[CW * NE];           // concatenated weights, 2.2 MB
__device__ float g_C[NB * NN * CW];         // q|k|w per token, 8.9 MB
__device__ float g_wbg2[NP * NH];           // Wb*pln_g, pair-interleaved [p/2][h][2]
__device__ float g_c1[NH];
__device__ float g_c2[NH];
__device__ float g_qkm[(size_t)NB * NH * NN * NN];   // qk + mask, 134 MB

__device__ __forceinline__ void ffma2(unsigned long long& d, unsigned long long a, unsigned long long b) {
    asm("fma.rn.f32x2 %0, %1, %2, %0;" : "+l"(d) : "l"(a), "l"(b));
}
__device__ __forceinline__ void unpack2(float& lo, float& hi, unsigned long long v) {
    asm("mov.b64 {%0, %1}, %2;" : "=f"(lo), "=f"(hi) : "l"(v));
}

// ---------------- prep: build Wcat, wbg2, c1, c2 ----------------
__global__ void prep_kernel(const float* __restrict__ Wq, const float* __restrict__ Wk,
                            const float* __restrict__ Wv, const float* __restrict__ Wf,
                            const float* __restrict__ Wb, const float* __restrict__ bb,
                            const float* __restrict__ pg, const float* __restrict__ pb)
{
    int r = blockIdx.x;
    int tid = threadIdx.x;
    if (r < 512) {
        for (int e = tid; e < NE; e += 256)
            g_Wcat[r * NE + e] = Wq[r * NE + e] * 0.25f;   // SCALING folded in
    } else if (r < 1024) {
        int rr = r - 512;
        for (int e = tid; e < NE; e += 256)
            g_Wcat[r * NE + e] = Wk[rr * NE + e];
    } else if (r < 1056) {
        int h = r - 1024;
        for (int e = tid; e < NE; e += 256) {
            float s = 0.f;
#pragma unroll
            for (int d = 0; d < ND; d++)
                s += Wf[h * ND + d] * Wv[(h * ND + d) * NE + e];
            g_Wcat[r * NE + e] = s;                        // Wvf
        }
    } else if (r < 1088) {
        for (int e = tid; e < NE; e += 256) g_Wcat[r * NE + e] = 0.f;
    } else if (r == 1088) {
        for (int t = tid; t < NP * NH; t += 256) {
            int p = t >> 5, h = t & 31;
            g_wbg2[(p >> 1) * 64 + h * 2 + (p & 1)] = Wb[h * NP + p] * pg[p];
        }
    } else {
        if (tid < NH) {
            int h = tid;
            float s1 = 0.f, s2 = 0.f;
            for (int p = 0; p < NP; p++) {
                float wv = Wb[h * NP + p];
                s1 += wv * pg[p];
                s2 += wv * pb[p];
            }
            g_c1[h] = s1;
            g_c2[h] = s2 + bb[h];
        }
    }
}

// ---------------- layernorm over E=512 ----------------
__global__ void ln_kernel(const float* __restrict__ q, const float* __restrict__ g,
                          const float* __restrict__ b)
{
    int row = blockIdx.x;
    int tid = threadIdx.x;
    const float* x = q + (size_t)row * NE;
    float4 v = *(const float4*)(x + tid * 4);
    float s  = v.x + v.y + v.z + v.w;
    float ss = v.x * v.x + v.y * v.y + v.z * v.z + v.w * v.w;
#pragma unroll
    for (int o = 16; o; o >>= 1) {
        s  += __shfl_xor_sync(0xffffffffu, s, o);
        ss += __shfl_xor_sync(0xffffffffu, ss, o);
    }
    __shared__ float rs[4], rss[4];
    int w = tid >> 5;
    if ((tid & 31) == 0) { rs[w] = s; rss[w] = ss; }
    __syncthreads();
    s  = rs[0] + rs[1] + rs[2] + rs[3];
    ss = rss[0] + rss[1] + rss[2] + rss[3];
    float mu   = s * (1.f / 512.f);
    float var  = ss * (1.f / 512.f) - mu * mu;
    float rstd = rsqrtf(var + 1e-5f);
    float4 gg = *(const float4*)(g + tid * 4);
    float4 bv = *(const float4*)(b + tid * 4);
    float4 o;
    o.x = (v.x - mu) * rstd * gg.x + bv.x;
    o.y = (v.y - mu) * rstd * gg.y + bv.y;
    o.z = (v.z - mu) * rstd * gg.z + bv.z;
    o.w = (v.w - mu) * rstd * gg.w + bv.w;
    *(float4*)(g_xn + (size_t)row * NE + tid * 4) = o;
}

// ---------------- GEMM: C[2048][1088] = xn @ Wcat^T ----------------
__global__ __launch_bounds__(256) void gemm_qkw_kernel()
{
    __shared__ float As[16][68];
    __shared__ float Bs[16][68];
    int m0 = blockIdx.x * 64, n0 = blockIdx.y * 64;
    int tid = threadIdx.x;
    int tm = tid >> 4, tn = tid & 15;
    int lr = tid >> 2, lc = tid & 3;
    float acc[4][4] = {};
    for (int k0 = 0; k0 < NE; k0 += 16) {
        float4 av = *(const float4*)&g_xn[(size_t)(m0 + lr) * NE + k0 + lc * 4];
        float4 bv = *(const float4*)&g_Wcat[(size_t)(n0 + lr) * NE + k0 + lc * 4];
        As[lc * 4 + 0][lr] = av.x; As[lc * 4 + 1][lr] = av.y;
        As[lc * 4 + 2][lr] = av.z; As[lc * 4 + 3][lr] = av.w;
        Bs[lc * 4 + 0][lr] = bv.x; Bs[lc * 4 + 1][lr] = bv.y;
        Bs[lc * 4 + 2][lr] = bv.z; Bs[lc * 4 + 3][lr] = bv.w;
        __syncthreads();
#pragma unroll
        for (int k = 0; k < 16; k++) {
            float4 a = *(const float4*)&As[k][tm * 4];
            float4 b = *(const float4*)&Bs[k][tn * 4];
            acc[0][0] += a.x * b.x; acc[0][1] += a.x * b.y; acc[0][2] += a.x * b.z; acc[0][3] += a.x * b.w;
            acc[1][0] += a.y * b.x; acc[1][1] += a.y * b.y; acc[1][2] += a.y * b.z; acc[1][3] += a.y * b.w;
            acc[2][0] += a.z * b.x; acc[2][1] += a.z * b.y; acc[2][2] += a.z * b.z; acc[2][3] += a.z * b.w;
            acc[3][0] += a.w * b.x; acc[3][1] += a.w * b.y; acc[3][2] += a.w * b.z; acc[3][3] += a.w * b.w;
        }
        __syncthreads();
    }
#pragma unroll
    for (int t = 0; t < 4; t++)
#pragma unroll
        for (int u = 0; u < 4; u++)
            g_C[(size_t)(m0 + tm * 4 + t) * CW + n0 + tn * 4 + u] = acc[t][u];
}

// ---------------- qk+mask kernel v2: 512 CTAs, 512 threads, MLP-4 ----------------
// grid (ichunk 0..3, h, b); thread = j; k in regs; 128 i per CTA, unroll 4.
__global__ __launch_bounds__(512) void qk_kernel(const float* __restrict__ mask)
{
    __shared__ float qs[128 * ND];   // 8 KB
    int ic = blockIdx.x, h = blockIdx.y, b = blockIdx.z;
    int tid = threadIdx.x;
    int j = tid;
    int i0 = ic * 128;

    {   // stage q rows [i0, i0+128) for head h: 512 threads x 1 float4
        int i = tid >> 2, d4 = tid & 3;
        float4 v = *(const float4*)&g_C[(size_t)(b * NN + i0 + i) * CW + h * ND + d4 * 4];
        *(float4*)&qs[i * ND + d4 * 4] = v;
    }
    const float* kr = g_C + (size_t)(b * NN + j) * CW + 512 + h * ND;
    float4 k0 = *(const float4*)(kr + 0);
    float4 k1 = *(const float4*)(kr + 4);
    float4 k2 = *(const float4*)(kr + 8);
    float4 k3 = *(const float4*)(kr + 12);
    __syncthreads();

    size_t base = (((size_t)(b * NH + h) * NN + i0)) * NN + j;
    const float* mrow = mask + base;
    float* orow = g_qkm + base;
#pragma unroll 2
    for (int ii = 0; ii < 128; ii += 4) {
        float mk[4];
#pragma unroll
        for (int t = 0; t < 4; t++) mk[t] = mrow[(size_t)(ii + t) * NN];
        float dv[4];
#pragma unroll
        for (int t = 0; t < 4; t++) {
            const float* q = &qs[(ii + t) * ND];
            float4 q0 = *(const float4*)(q + 0);
            float4 q1 = *(const float4*)(q + 4);
            float4 q2 = *(const float4*)(q + 8);
            float4 q3 = *(const float4*)(q + 12);
            dv[t] =
                q0.x * k0.x + q0.y * k0.y + q0.z * k0.z + q0.w * k0.w +
                q1.x * k1.x + q1.y * k1.y + q1.z * k1.z + q1.w * k1.w +
                q2.x * k2.x + q2.y * k2.y + q2.z * k2.z + q2.w * k2.w +
                q3.x * k3.x + q3.y * k3.y + q3.z * k3.z + q3.w * k3.w;
        }
#pragma unroll
        for (int t = 0; t < 4; t++) orow[(size_t)(ii + t) * NN] = dv[t] + mk[t];
    }
}

// ---------------- fused attention kernel v4 ----------------
// CTA per (b,i), 3 CTAs/SM. Flash online softmax, f32x2 bias GEMM.
// Staging: thread owns ONE pair row (row = tid>>2) -> private LN stats, 2 shfl.
#define SM_FLOATS (64 * 132 + 4096 + 32 * 68 + 64 + 64 + 1280)

__global__ __launch_bounds__(256, 3) void fused_attn_kernel(
    const float* __restrict__ pair, const float* __restrict__ dpos,
    float* __restrict__ out)
{
    extern __shared__ float sm[];
    float* pair_s = sm;                        // [64][132]
    float* wbg2_s = pair_s + 64 * 132;         // [p/2][32][2]
    float* qkm_s  = wbg2_s + 4096;             // [32][68]
    float* mu_s   = qkm_s + 32 * 68;           // [64]
    float* rs_s   = mu_s + 64;                 // [64]
    float* mrg    = rs_s + 64;                 // [8][32][5]

    int bi = blockIdx.x;                       // b*512 + i
    int b = bi >> 9, i = bi & 511;
    int tid = threadIdx.x;
    int jg = tid >> 3, hg = tid & 7;
    int hg4 = hg * 4;
    int srow = tid >> 2, sqtr = tid & 3;       // staging: one row per 4 threads

    for (int t = tid; t < NP * NH; t += 256) wbg2_s[t] = g_wbg2[t];
    float4 c1v = *(const float4*)&g_c1[hg4];
    float4 c2v = *(const float4*)&g_c2[hg4];
    float c1a[4] = { c1v.x, c1v.y, c1v.z, c1v.w };
    float c2a[4] = { c2v.x, c2v.y, c2v.z, c2v.w };

    float m_r[4] = { -1e30f, -1e30f, -1e30f, -1e30f };
    float z_r[4] = { 0.f, 0.f, 0.f, 0.f };
    float a0_r[4] = {}, a1_r[4] = {}, a2_r[4] = {};

    const float* pbase = pair + (size_t)bi * NN * NP;
    const float* qkbase = g_qkm + ((size_t)b * NH * NN + i) * NN;  // + h*NN*NN + j

    for (int tile = 0; tile < NTILE; ++tile) {
        int j0 = tile * JT;
        __syncthreads();
        // ---- stage pair tile: thread loads 8 float4 from ONE row; private stats ----
        {
            const float* prow = pbase + (size_t)(j0 + srow) * NP;
            float s = 0.f, ss = 0.f;
#pragma unroll
            for (int it = 0; it < 8; ++it) {
                int p4 = sqtr + it * 4;
                float4 v = *(const float4*)(prow + p4 * 4);
                *(float4*)&pair_s[srow * 132 + p4 * 4] = v;
                s  += v.x + v.y + v.z + v.w;
                ss += v.x * v.x + v.y * v.y + v.z * v.z + v.w * v.w;
            }
            s  += __shfl_xor_sync(0xffffffffu, s, 1);
            ss += __shfl_xor_sync(0xffffffffu, ss, 1);
            s  += __shfl_xor_sync(0xffffffffu, s, 2);
            ss += __shfl_xor_sync(0xffffffffu, ss, 2);
            if (sqtr == 0) {
                float mu  = s * (1.f / 128.f);
                float var = ss * (1.f / 128.f) - mu * mu;
                mu_s[srow] = mu;
                rs_s[srow] = rsqrtf(var + 1e-5f);
            }
        }
        // ---- stage qkm tile [32h][64j] ----
#pragma unroll
        for (int it = 0; it < 2; ++it) {
            int idx = it * 256 + tid;
            int h = idx >> 4, j4 = idx & 15;
            float4 v = *(const float4*)(qkbase + (size_t)h * NN * NN + j0 + j4 * 4);
            *(float4*)&qkm_s[h * 68 + j4 * 4] = v;
        }
        __syncthreads();
        // ---- bias GEMM in f32x2: 2j x 4h, K=128 as 64 p-pairs ----
        unsigned long long acc2[2][4] = {};
        const ulonglong2* pa0 = (const ulonglong2*)&pair_s[(jg * 2 + 0) * 132];
        const ulonglong2* pa1 = (const ulonglong2*)&pair_s[(jg * 2 + 1) * 132];
        const unsigned long long* wb = (const unsigned long long*)wbg2_s;  // [p2][32h]
#pragma unroll 8
        for (int p4 = 0; p4 < 32; ++p4) {
            ulonglong2 a0 = pa0[p4];
            ulonglong2 a1 = pa1[p4];
            int p2 = p4 * 2;
            ulonglong2 wA0 = *(const ulonglong2*)&wb[(size_t)(p2 + 0) * 32 + hg4];
            ulonglong2 wB0 = *(const ulonglong2*)&wb[(size_t)(p2 + 0) * 32 + hg4 + 2];
            ulonglong2 wA1 = *(const ulonglong2*)&wb[(size_t)(p2 + 1) * 32 + hg4];
            ulonglong2 wB1 = *(const ulonglong2*)&wb[(size_t)(p2 + 1) * 32 + hg4 + 2];
            ffma2(acc2[0][0], a0.x, wA0.x); ffma2(acc2[0][1], a0.x, wA0.y);
            ffma2(acc2[0][2], a0.x, wB0.x); ffma2(acc2[0][3], a0.x, wB0.y);
            ffma2(acc2[1][0], a1.x, wA0.x); ffma2(acc2[1][1], a1.x, wA0.y);
            ffma2(acc2[1][2], a1.x, wB0.x); ffma2(acc2[1][3], a1.x, wB0.y);
            ffma2(acc2[0][0], a0.y, wA1.x); ffma2(acc2[0][1], a0.y, wA1.y);
            ffma2(acc2[0][2], a0.y, wB1.x); ffma2(acc2[0][3], a0.y, wB1.y);
            ffma2(acc2[1][0], a1.y, wA1.x); ffma2(acc2[1][1], a1.y, wA1.y);
            ffma2(acc2[1][2], a1.y, wB1.x); ffma2(acc2[1][3], a1.y, wB1.y);
        }
        // ---- epilogue: affine LN bias + qkm; online softmax + force accum ----
#pragma unroll
        for (int t = 0; t < 2; t++) {
            int jl = jg * 2 + t;
            int j  = j0 + jl;
            float muv = mu_s[jl], rsv = rs_s[jl];
            float4 w4 = *(const float4*)(g_C + ((size_t)(b * NN + j)) * CW + 1024 + hg4);
            const float* dp = dpos + ((size_t)bi * NN + j) * 3;
            float dp0 = dp[0], dp1 = dp[1], dp2 = dp[2];
            float accf[4];
            {
                float lo, hi;
                unpack2(lo, hi, acc2[t][0]); accf[0] = lo + hi;
                unpack2(lo, hi, acc2[t][1]); accf[1] = lo + hi;
                unpack2(lo, hi, acc2[t][2]); accf[2] = lo + hi;
                unpack2(lo, hi, acc2[t][3]); accf[3] = lo + hi;
            }
            float wr[4] = { w4.x, w4.y, w4.z, w4.w };
#pragma unroll
            for (int u = 0; u < 4; u++) {
                int h = hg4 + u;
                float qkm = qkm_s[h * 68 + jl];
                float lv = rsv * (accf[u] - muv * c1a[u]) + c2a[u] + qkm;
                float nm = fmaxf(m_r[u], lv);
                float sc = __expf(m_r[u] - nm);
                float e  = __expf(lv - nm);
                m_r[u] = nm;
                z_r[u] = z_r[u] * sc + e;
                float ew = e * wr[u];
                a0_r[u] = a0_r[u] * sc + ew * dp0;
                a1_r[u] = a1_r[u] * sc + ew * dp1;
                a2_r[u] = a2_r[u] * sc + ew * dp2;
            }
        }
    }

    // ---- flash merge across 32 threads sharing each head (shfl 8,16) ----
#pragma unroll
    for (int u = 0; u < 4; u++) {
#pragma unroll
        for (int off = 8; off <= 16; off <<= 1) {
            float om = __shfl_xor_sync(0xffffffffu, m_r[u], off);
            float oz = __shfl_xor_sync(0xffffffffu, z_r[u], off);
            float o0 = __shfl_xor_sync(0xffffffffu, a0_r[u], off);
            float o1 = __shfl_xor_sync(0xffffffffu, a1_r[u], off);
            float o2 = __shfl_xor_sync(0xffffffffu, a2_r[u], off);
            float M = fmaxf(m_r[u], om);
            float s1 = __expf(m_r[u] - M);
            float s2 = __expf(om - M);
            z_r[u]  = z_r[u]  * s1 + oz * s2;
            a0_r[u] = a0_r[u] * s1 + o0 * s2;
            a1_r[u] = a1_r[u] * s1 + o1 * s2;
            a2_r[u] = a2_r[u] * s1 + o2 * s2;
            m_r[u] = M;
        }
    }
    __syncthreads();
    {
        int w = tid >> 5, lane = tid & 31;
        if (lane < 8) {
#pragma unroll
            for (int u = 0; u < 4; u++) {
                int h = lane * 4 + u;
                float* e = &mrg[(w * 32 + h) * 5];
                e[0] = m_r[u]; e[1] = z_r[u]; e[2] = a0_r[u]; e[3] = a1_r[u]; e[4] = a2_r[u];
            }
        }
    }
    __syncthreads();
    if (tid < 32) {
        int h = tid;
        float M = -1e30f, Z = 0.f, A0 = 0.f, A1 = 0.f, A2 = 0.f;
#pragma unroll
        for (int w = 0; w < 8; w++) {
            const float* e = &mrg[(w * 32 + h) * 5];
            float om = e[0];
            float nM = fmaxf(M, om);
            float s1 = __expf(M - nM);
            float s2 = __expf(om - nM);
            Z  = Z * s1 + e[1] * s2;
            A0 = A0 * s1 + e[2] * s2;
            A1 = A1 * s1 + e[3] * s2;
            A2 = A2 * s1 + e[4] * s2;
            M = nM;
        }
        float inv = 1.f / Z;
        float f0 = A0 * inv, f1 = A1 * inv, f2 = A2 * inv;
#pragma unroll
        for (int o = 16; o; o >>= 1) {
            f0 += __shfl_xor_sync(0xffffffffu, f0, o);
            f1 += __shfl_xor_sync(0xffffffffu, f1, o);
            f2 += __shfl_xor_sync(0xffffffffu, f2, o);
        }
        if (tid == 0) {
            out[(size_t)bi * 3 + 0] = f0;
            out[(size_t)bi * 3 + 1] = f1;
            out[(size_t)bi * 3 + 2] = f2;
        }
    }
}

// ---------------- launcher ----------------
extern "C" void kernel_launch(void* const* d_in, const int* in_sizes, int n_in,
                              void* d_out, int out_size)
{
    (void)in_sizes; (void)n_in; (void)out_size;
    const float* query  = (const float*)d_in[0];
    const float* pair   = (const float*)d_in[1];
    const float* mask   = (const float*)d_in[2];
    const float* dpos   = (const float*)d_in[3];
    const float* ln_g   = (const float*)d_in[4];
    const float* ln_b   = (const float*)d_in[5];
    const float* Wq     = (const float*)d_in[6];
    const float* Wk     = (const float*)d_in[7];
    const float* Wv     = (const float*)d_in[8];
    const float* pln_g  = (const float*)d_in[9];
    const float* pln_b  = (const float*)d_in[10];
    const float* Wb     = (const float*)d_in[11];
    const float* bb     = (const float*)d_in[12];
    const float* Wf     = (const float*)d_in[13];
    float* out = (float*)d_out;

    static_assert(SM_FLOATS * 4 <= 66 * 1024, "smem budget for 3 CTAs/SM");
    cudaFuncSetAttribute(fused_attn_kernel,
                         cudaFuncAttributeMaxDynamicSharedMemorySize, SM_FLOATS * 4);

    prep_kernel<<<1090, 256>>>(Wq, Wk, Wv, Wf, Wb, bb, pln_g, pln_b);
    ln_kernel<<<NB * NN, 128>>>(query, ln_g, ln_b);
    gemm_qkw_kernel<<<dim3(32, 17), 256>>>();
    qk_kernel<<<dim3(4, NH, NB), 512>>>(mask);
    fused_attn_kernel<<<NB * NN, 256, SM_FLOATS * 4>>>(pair, dpos, out);
}